// round 15
// baseline (speedup 1.0000x reference)
#include <cuda_runtime.h>
#include <cstdint>
#include <cstddef>

// Problem constants (fixed shapes)
#define SEQ_L   8192
#define DMODEL  1024
#define NBATCH  2
#define NGROUP  256
#define LCACHE  128

// Tiling: 256 timesteps x 32 channels per CTA, 256 threads
#define T_TILE  256
#define NPAIR   16                       // 16 channel pairs = 32 channels per CTA
#define ZSTR    386                      // EVEN row stride (float2) -> 16B-aligned rows
#define KSTR2   130                      // duplicated-filter row stride (float2, even)
#define NTHREADS 256

#define SMEM_BYTES (NPAIR * ZSTR * (int)sizeof(float2) + 8 * KSTR2 * (int)sizeof(float2))

// Decayed filter, precomputed once per launch: k[g,tau] = h[g,tau]*exp(-10^(2g/255) * tau/127)
__device__ float g_k[NGROUP * LCACHE];

__global__ void build_filter(const float* __restrict__ h) {
    int g = blockIdx.x;
    int tau = threadIdx.x;
    float decay = exp10f(2.0f * (float)g * (1.0f / 255.0f));
    float t = (float)tau * (1.0f / 127.0f);
    g_k[g * LCACHE + tau] = h[g * LCACHE + tau] * expf(-decay * t);
}

typedef unsigned long long ull;

__device__ __forceinline__ ull ld2(const float2* p) {
    return *reinterpret_cast<const ull*>(p);
}
__device__ __forceinline__ void fma2(ull& d, ull a, ull b) {
    asm("fma.rn.f32x2 %0, %1, %2, %0;" : "+l"(d) : "l"(a), "l"(b));
}
// 16B load of two packed float2 (requires 16B-aligned address)
__device__ __forceinline__ ulonglong2 ld4(const float2* p) {
    return *reinterpret_cast<const ulonglong2*>(p);
}

__global__ __launch_bounds__(NTHREADS, 3) void hyena_main(
    const float* __restrict__ x1g, const float* __restrict__ x2g,
    const float* __restrict__ vg,  const float* __restrict__ biasg,
    float* __restrict__ outg)
{
    extern __shared__ float2 sm[];
    float2* z_sh = sm;                          // [NPAIR][ZSTR] (rows 16B aligned)
    float2* k_sh = z_sh + NPAIR * ZSTR;         // [8][KSTR2] duplicated (k,k)

    const int tid   = threadIdx.x;
    const int b     = blockIdx.z;
    const int dblk  = blockIdx.y;                 // 0..31
    const int t0    = blockIdx.x * T_TILE;        // 0..7936
    const int dbase = dblk * (2 * NPAIR);         // 32 channels per block
    const int gbase = dbase >> 2;                 // first group of this CTA

    // Effective tap count (uniform per CTA): keep exp(-decay*tau/127) >= e^-6.
    const float decay_min = exp10f(2.0f * (float)gbase * (1.0f / 255.0f));
    const int Lmax = min(128, (int)(762.0f / decay_min) + 1);
    const int NC = min(6, max(1, (Lmax - 8 + 19) / 20));

    // ---- stage filter duplicated: 8 groups x 128 taps as (k,k) float2 ----
    for (int i = tid; i < 8 * LCACHE; i += NTHREADS) {
        int gl = i >> 7, tau = i & 127;
        float kv = g_k[(gbase + gl) * LCACHE + tau];
        k_sh[gl * KSTR2 + tau] = make_float2(kv, kv);
    }

    // ---- stage z = x2*v for window [t0-128, t0+256): 96 float4 per row ----
    {
        const int p = tid >> 4;                   // pair 0..15
        const int s = tid & 15;                   // 16 threads per pair
        const int d0 = dbase + 2 * p;
        const size_t r0 = ((size_t)b * DMODEL + d0) * SEQ_L;
        const size_t r1 = r0 + SEQ_L;
        float2* zrow = z_sh + p * ZSTR;
        if (t0 >= 128) {
            #pragma unroll 3
            for (int c = 0; c < 6; ++c) {
                const int idx = c * 16 + s;       // float4 index 0..95
                const int tg  = t0 - 128 + 4 * idx;
                float4 a0 = *reinterpret_cast<const float4*>(x2g + r0 + tg);
                float4 a1 = *reinterpret_cast<const float4*>(x2g + r1 + tg);
                float4 v0 = *reinterpret_cast<const float4*>(vg  + r0 + tg);
                float4 v1 = *reinterpret_cast<const float4*>(vg  + r1 + tg);
                float4* zp = reinterpret_cast<float4*>(zrow + 4 * idx);  // 16B aligned
                zp[0] = make_float4(a0.x * v0.x, a1.x * v1.x, a0.y * v0.y, a1.y * v1.y);
                zp[1] = make_float4(a0.z * v0.z, a1.z * v1.z, a0.w * v0.w, a1.w * v1.w);
            }
        } else {
            #pragma unroll 3
            for (int c = 0; c < 6; ++c) {
                const int idx = c * 16 + s;
                const int tg  = t0 - 128 + 4 * idx;
                float4 a0, a1, v0, v1;
                if (tg >= 0) {
                    a0 = *reinterpret_cast<const float4*>(x2g + r0 + tg);
                    a1 = *reinterpret_cast<const float4*>(x2g + r1 + tg);
                    v0 = *reinterpret_cast<const float4*>(vg  + r0 + tg);
                    v1 = *reinterpret_cast<const float4*>(vg  + r1 + tg);
                } else {
                    a0 = a1 = v0 = v1 = make_float4(0.f, 0.f, 0.f, 0.f);
                }
                float4* zp = reinterpret_cast<float4*>(zrow + 4 * idx);
                zp[0] = make_float4(a0.x * v0.x, a1.x * v1.x, a0.y * v0.y, a1.y * v1.y);
                zp[1] = make_float4(a0.z * v0.z, a1.z * v1.z, a0.w * v0.w, a1.w * v1.w);
            }
        }
    }
    __syncthreads();

    // ---- compute: each thread owns 1 channel pair x 16 timesteps ----
    // Window index w = 128 - tau + j (j = output 0..15), stored at zbase + w,
    // zbase = zrow + 16*tslice (EVEN float2 offset -> 16B aligned for even w).
    // Ring slot = w % 20; period 5 groups (20 taps). Refill before group g writes
    // w in [124-4g, 128-4g): slot(124-4g) aliases w=144-4g (dead after group g-1),
    // slots 125..127-4g alias 145..147-4g (dead after group g-1). Same liveness
    // proof as the validated descending refill, shifted by +1.
    const int pair   = tid & 15;
    const int tslice = tid >> 4;                   // 0..15
    const float2* krow = k_sh + (pair >> 1) * KSTR2;
    const float2* zrow = z_sh + pair * ZSTR;
    const float2* zbase = zrow + tslice * 16;

    ull acc[16];
    #pragma unroll
    for (int j = 0; j < 16; ++j) acc[j] = 0ull;

    ull r[20];
    // init: w in [124, 144) via 10x 16B loads
    #pragma unroll
    for (int i = 0; i < 10; ++i) {
        const ulonglong2 q = ld4(zbase + 124 + 2 * i);
        r[(124 + 2 * i) % 20] = q.x;
        r[(125 + 2 * i) % 20] = q.y;
    }

    // head group 0: tau = 0..3 (k duplicated: one 16B load = 2 packed taps)
    {
        const ulonglong2 ka = ld4(krow + 0);       // taus 0,1
        const ulonglong2 kb = ld4(krow + 2);       // taus 2,3
        #pragma unroll
        for (int j = 0; j < 16; ++j) fma2(acc[j], ka.x, r[(128 + j) % 20]);
        #pragma unroll
        for (int j = 0; j < 16; ++j) fma2(acc[j], ka.y, r[(127 + j) % 20]);
        #pragma unroll
        for (int j = 0; j < 16; ++j) fma2(acc[j], kb.x, r[(126 + j) % 20]);
        #pragma unroll
        for (int j = 0; j < 16; ++j) fma2(acc[j], kb.y, r[(125 + j) % 20]);
    }
    // head group 1: tau = 4..7, refill w in [120,124) first
    {
        const ulonglong2 z0 = ld4(zbase + 120);
        const ulonglong2 z1 = ld4(zbase + 122);
        r[(120) % 20] = z0.x;  r[(121) % 20] = z0.y;
        r[(122) % 20] = z1.x;  r[(123) % 20] = z1.y;
        const ulonglong2 ka = ld4(krow + 4);       // taus 4,5
        const ulonglong2 kb = ld4(krow + 6);       // taus 6,7
        #pragma unroll
        for (int j = 0; j < 16; ++j) fma2(acc[j], ka.x, r[(124 + j) % 20]);
        #pragma unroll
        for (int j = 0; j < 16; ++j) fma2(acc[j], ka.y, r[(123 + j) % 20]);
        #pragma unroll
        for (int j = 0; j < 16; ++j) fma2(acc[j], kb.x, r[(122 + j) % 20]);
        #pragma unroll
        for (int j = 0; j < 16; ++j) fma2(acc[j], kb.y, r[(121 + j) % 20]);
    }
    // super-groups: iteration c covers taus 8+20c .. 27+20c (5 groups of 4)
    {
        const float2* zc = zbase;
        const float2* kc = krow + 8;
        #pragma unroll 1
        for (int c = 0; c < NC; ++c) {
            #pragma unroll
            for (int u = 0; u < 5; ++u) {
                // refill w_rel in [116-4u, 120-4u) (even start, 2x 16B)
                {
                    const ulonglong2 z0 = ld4(zc + (116 - 4 * u));
                    const ulonglong2 z1 = ld4(zc + (118 - 4 * u));
                    r[(116 - 4 * u) % 20] = z0.x;  r[(117 - 4 * u) % 20] = z0.y;
                    r[(118 - 4 * u) % 20] = z1.x;  r[(119 - 4 * u) % 20] = z1.y;
                }
                const ulonglong2 ka = ld4(kc + 4 * u);      // taus 8+20c+4u, +1
                const ulonglong2 kb = ld4(kc + 4 * u + 2);  // taus +2, +3
                #pragma unroll
                for (int j = 0; j < 16; ++j) fma2(acc[j], ka.x, r[(120 - 4 * u + j) % 20]);
                #pragma unroll
                for (int j = 0; j < 16; ++j) fma2(acc[j], ka.y, r[(119 - 4 * u + j) % 20]);
                #pragma unroll
                for (int j = 0; j < 16; ++j) fma2(acc[j], kb.x, r[(118 - 4 * u + j) % 20]);
                #pragma unroll
                for (int j = 0; j < 16; ++j) fma2(acc[j], kb.y, r[(117 - 4 * u + j) % 20]);
            }
            zc -= 20;
            kc += 20;
        }
    }

    // ---- epilogue: out = (y + z*bias) * x1 ----
    const int d0e = dbase + pair * 2;
    const float2 bb = *reinterpret_cast<const float2*>(biasg + d0e);
    const ull bpk = *reinterpret_cast<const ull*>(&bb);

    const float* x1r0 = x1g + ((size_t)b * DMODEL + d0e) * SEQ_L + t0 + tslice * 16;
    const float* x1r1 = x1r0 + SEQ_L;
    float4 xa[4], xb[4];
    #pragma unroll
    for (int q = 0; q < 4; ++q) {
        xa[q] = *reinterpret_cast<const float4*>(x1r0 + 4 * q);
        xb[q] = *reinterpret_cast<const float4*>(x1r1 + 4 * q);
    }

    float* op = outg + ((size_t)b * SEQ_L + (size_t)(t0 + tslice * 16)) * DMODEL + d0e;
    #pragma unroll
    for (int q = 0; q < 8; ++q) {
        const ulonglong2 zz = ld4(zbase + 128 + 2 * q);   // z[t] for j=2q, 2q+1
        const int j0 = 2 * q, j1 = 2 * q + 1;
        fma2(acc[j0], zz.x, bpk);
        fma2(acc[j1], zz.y, bpk);
        float2 r0v = *reinterpret_cast<float2*>(&acc[j0]);
        float2 r1v = *reinterpret_cast<float2*>(&acc[j1]);
        const float* pxa = reinterpret_cast<const float*>(&xa[j0 >> 2]);
        const float* pxb = reinterpret_cast<const float*>(&xb[j0 >> 2]);
        r0v.x *= pxa[j0 & 3];  r0v.y *= pxb[j0 & 3];
        r1v.x *= pxa[j1 & 3];  r1v.y *= pxb[j1 & 3];
        *reinterpret_cast<float2*>(op + (size_t)j0 * DMODEL) = r0v;
        *reinterpret_cast<float2*>(op + (size_t)j1 * DMODEL) = r1v;
    }
}

extern "C" void kernel_launch(void* const* d_in, const int* in_sizes, int n_in,
                              void* d_out, int out_size) {
    const float* x1 = (const float*)d_in[0];
    const float* x2 = (const float*)d_in[1];
    const float* v  = (const float*)d_in[2];
    const float* h  = (const float*)d_in[3];
    const float* cb = (const float*)d_in[4];
    float* out = (float*)d_out;

    cudaFuncSetAttribute(hyena_main, cudaFuncAttributeMaxDynamicSharedMemorySize, SMEM_BYTES);

    build_filter<<<NGROUP, LCACHE>>>(h);

    dim3 grid(SEQ_L / T_TILE, DMODEL / (2 * NPAIR), NBATCH);  // (32, 32, 2)
    hyena_main<<<grid, NTHREADS, SMEM_BYTES>>>(x1, x2, v, cb, out);
}

// round 16
// speedup vs baseline: 1.0966x; 1.0966x over previous
#include <cuda_runtime.h>
#include <cstdint>
#include <cstddef>

// Problem constants (fixed shapes)
#define SEQ_L   8192
#define DMODEL  1024
#define NBATCH  2
#define NGROUP  256
#define LCACHE  128

// Tiling: 256 timesteps x 32 channels per CTA, 256 threads
#define T_TILE  256
#define NPAIR   16                       // 16 channel pairs = 32 channels per CTA
#define ZSTR    385                      // ODD row stride (float2) -> conflict-free LDS.64
#define KSTR2   130                      // duplicated-filter row stride (float2, even -> 16B rows)
#define NTHREADS 256

#define SMEM_BYTES (NPAIR * ZSTR * (int)sizeof(float2) + 8 * KSTR2 * (int)sizeof(float2))

// Decayed filter, precomputed once per launch: k[g,tau] = h[g,tau]*exp(-10^(2g/255) * tau/127)
__device__ float g_k[NGROUP * LCACHE];

__global__ void build_filter(const float* __restrict__ h) {
    int g = blockIdx.x;
    int tau = threadIdx.x;
    float decay = exp10f(2.0f * (float)g * (1.0f / 255.0f));
    float t = (float)tau * (1.0f / 127.0f);
    g_k[g * LCACHE + tau] = h[g * LCACHE + tau] * expf(-decay * t);
}

typedef unsigned long long ull;

__device__ __forceinline__ ull ld2(const float2* p) {
    return *reinterpret_cast<const ull*>(p);
}
__device__ __forceinline__ void fma2(ull& d, ull a, ull b) {
    asm("fma.rn.f32x2 %0, %1, %2, %0;" : "+l"(d) : "l"(a), "l"(b));
}
// 16B load of two packed float2 (requires 16B-aligned address); operands consumed
// directly by FFMA2 (no ring placement -> no MOV penalty)
__device__ __forceinline__ ulonglong2 ld4(const float2* p) {
    return *reinterpret_cast<const ulonglong2*>(p);
}

__global__ __launch_bounds__(NTHREADS, 3) void hyena_main(
    const float* __restrict__ x1g, const float* __restrict__ x2g,
    const float* __restrict__ vg,  const float* __restrict__ biasg,
    float* __restrict__ outg)
{
    extern __shared__ float2 sm[];
    float2* z_sh = sm;                          // [NPAIR][ZSTR] odd stride, ld2-only
    float2* k_sh = z_sh + NPAIR * ZSTR;         // [8][KSTR2] duplicated (k,k), 16B rows

    const int tid   = threadIdx.x;
    const int b     = blockIdx.z;
    const int dblk  = blockIdx.y;                 // 0..31
    const int t0    = blockIdx.x * T_TILE;        // 0..7936
    const int dbase = dblk * (2 * NPAIR);         // 32 channels per block
    const int gbase = dbase >> 2;                 // first group of this CTA

    // Effective tap count (uniform per CTA): keep exp(-decay*tau/127) >= e^-6.
    const float decay_min = exp10f(2.0f * (float)gbase * (1.0f / 255.0f));
    const int Lmax = min(128, (int)(762.0f / decay_min) + 1);
    const int NC = min(6, max(1, (Lmax - 8 + 19) / 20));

    // ---- stage filter duplicated: 8 groups x 128 taps as (k,k) float2 ----
    for (int i = tid; i < 8 * LCACHE; i += NTHREADS) {
        int gl = i >> 7, tau = i & 127;
        float kv = g_k[(gbase + gl) * LCACHE + tau];
        k_sh[gl * KSTR2 + tau] = make_float2(kv, kv);
    }

    // ---- stage z = x2*v for window [t0-128, t0+256): 96 float4 per row ----
    {
        const int p = tid >> 4;                   // pair 0..15
        const int s = tid & 15;                   // 16 threads per pair
        const int d0 = dbase + 2 * p;
        const size_t r0 = ((size_t)b * DMODEL + d0) * SEQ_L;
        const size_t r1 = r0 + SEQ_L;
        float2* zrow = z_sh + p * ZSTR;
        if (t0 >= 128) {
            // interior tile: uniform fast path (31/32 CTAs)
            #pragma unroll 3
            for (int c = 0; c < 6; ++c) {
                const int idx = c * 16 + s;       // float4 index 0..95
                const int tg  = t0 - 128 + 4 * idx;
                float4 a0 = *reinterpret_cast<const float4*>(x2g + r0 + tg);
                float4 a1 = *reinterpret_cast<const float4*>(x2g + r1 + tg);
                float4 v0 = *reinterpret_cast<const float4*>(vg  + r0 + tg);
                float4 v1 = *reinterpret_cast<const float4*>(vg  + r1 + tg);
                float2* zp = zrow + 4 * idx;
                zp[0] = make_float2(a0.x * v0.x, a1.x * v1.x);
                zp[1] = make_float2(a0.y * v0.y, a1.y * v1.y);
                zp[2] = make_float2(a0.z * v0.z, a1.z * v1.z);
                zp[3] = make_float2(a0.w * v0.w, a1.w * v1.w);
            }
        } else {
            #pragma unroll 3
            for (int c = 0; c < 6; ++c) {
                const int idx = c * 16 + s;
                const int tg  = t0 - 128 + 4 * idx;
                float4 a0, a1, v0, v1;
                if (tg >= 0) {
                    a0 = *reinterpret_cast<const float4*>(x2g + r0 + tg);
                    a1 = *reinterpret_cast<const float4*>(x2g + r1 + tg);
                    v0 = *reinterpret_cast<const float4*>(vg  + r0 + tg);
                    v1 = *reinterpret_cast<const float4*>(vg  + r1 + tg);
                } else {
                    a0 = a1 = v0 = v1 = make_float4(0.f, 0.f, 0.f, 0.f);
                }
                float2* zp = zrow + 4 * idx;
                zp[0] = make_float2(a0.x * v0.x, a1.x * v1.x);
                zp[1] = make_float2(a0.y * v0.y, a1.y * v1.y);
                zp[2] = make_float2(a0.z * v0.z, a1.z * v1.z);
                zp[3] = make_float2(a0.w * v0.w, a1.w * v1.w);
            }
        }
    }
    __syncthreads();

    // ---- compute: each thread owns 1 channel pair x 16 timesteps ----
    const int pair   = tid & 15;
    const int tslice = tid >> 4;                   // 0..15
    const int tb_loc = 128 + tslice * 16;          // local z index of first output t
    const float2* krow = k_sh + (pair >> 1) * KSTR2;
    const float2* zrow = z_sh + pair * ZSTR;
    const float2* zbase = zrow + (tb_loc - 127);

    ull acc[16];
    #pragma unroll
    for (int j = 0; j < 16; ++j) acc[j] = 0ull;

    // tau-ascending ring (slot = window index % 20); refill before each group
    // clobbers slots last used two groups earlier (proven liveness). Head taus
    // 0..7, then NC super-groups of 20 taps with compile-time slot maps.
    // z refills stay LDS.64 straight into ring registers (no MOV penalty).
    ull r[20];
    #pragma unroll
    for (int i2 = 0; i2 < 19; ++i2)
        r[(124 + i2) % 20] = ld2(zbase + 124 + i2);

    // head group 0: tau = 0..3 (duplicated k: one 16B load = 2 packed taps)
    {
        const ulonglong2 ka = ld4(krow + 0);       // taus 0,1
        const ulonglong2 kb = ld4(krow + 2);       // taus 2,3
        #pragma unroll
        for (int j = 0; j < 16; ++j) fma2(acc[j], ka.x, r[(127 + j) % 20]);
        #pragma unroll
        for (int j = 0; j < 16; ++j) fma2(acc[j], ka.y, r[(126 + j) % 20]);
        #pragma unroll
        for (int j = 0; j < 16; ++j) fma2(acc[j], kb.x, r[(125 + j) % 20]);
        #pragma unroll
        for (int j = 0; j < 16; ++j) fma2(acc[j], kb.y, r[(124 + j) % 20]);
    }
    // head group 1: tau = 4..7, refill 120..123 first
    {
        #pragma unroll
        for (int m = 0; m < 4; ++m) r[(120 + m) % 20] = ld2(zbase + 120 + m);
        const ulonglong2 ka = ld4(krow + 4);       // taus 4,5
        const ulonglong2 kb = ld4(krow + 6);       // taus 6,7
        #pragma unroll
        for (int j = 0; j < 16; ++j) fma2(acc[j], ka.x, r[(123 + j) % 20]);
        #pragma unroll
        for (int j = 0; j < 16; ++j) fma2(acc[j], ka.y, r[(122 + j) % 20]);
        #pragma unroll
        for (int j = 0; j < 16; ++j) fma2(acc[j], kb.x, r[(121 + j) % 20]);
        #pragma unroll
        for (int j = 0; j < 16; ++j) fma2(acc[j], kb.y, r[(120 + j) % 20]);
    }
    // super-groups: iteration c covers taus 8+20c .. 27+20c
    {
        const float2* zc = zbase;
        const float2* kc = krow + 8;
        #pragma unroll 1
        for (int c = 0; c < NC; ++c) {
            #pragma unroll
            for (int u = 0; u < 5; ++u) {
                #pragma unroll
                for (int m = 0; m < 4; ++m)
                    r[(116 - 4 * u + m) % 20] = ld2(zc + (116 - 4 * u + m));
                const ulonglong2 ka = ld4(kc + 4 * u);      // taus 8+20c+4u, +1
                const ulonglong2 kb = ld4(kc + 4 * u + 2);  // taus +2, +3
                #pragma unroll
                for (int j = 0; j < 16; ++j) fma2(acc[j], ka.x, r[(119 - 4 * u + j) % 20]);
                #pragma unroll
                for (int j = 0; j < 16; ++j) fma2(acc[j], ka.y, r[(118 - 4 * u + j) % 20]);
                #pragma unroll
                for (int j = 0; j < 16; ++j) fma2(acc[j], kb.x, r[(117 - 4 * u + j) % 20]);
                #pragma unroll
                for (int j = 0; j < 16; ++j) fma2(acc[j], kb.y, r[(116 - 4 * u + j) % 20]);
            }
            zc -= 20;
            kc += 20;
        }
    }

    // ---- epilogue: out = (y + z*bias) * x1 ----
    const int d0e = dbase + pair * 2;
    const float2 bb = *reinterpret_cast<const float2*>(biasg + d0e);
    const ull bpk = *reinterpret_cast<const ull*>(&bb);

    const float* x1r0 = x1g + ((size_t)b * DMODEL + d0e) * SEQ_L + t0 + tslice * 16;
    const float* x1r1 = x1r0 + SEQ_L;
    float4 xa[4], xb[4];
    #pragma unroll
    for (int q = 0; q < 4; ++q) {
        xa[q] = *reinterpret_cast<const float4*>(x1r0 + 4 * q);
        xb[q] = *reinterpret_cast<const float4*>(x1r1 + 4 * q);
    }

    float* op = outg + ((size_t)b * SEQ_L + (size_t)(t0 + tslice * 16)) * DMODEL + d0e;
    #pragma unroll
    for (int j = 0; j < 16; ++j) {
        const ull zt = ld2(zrow + (tb_loc + j));   // z[t]
        fma2(acc[j], zt, bpk);                     // y + z*bias
        float2 res = *reinterpret_cast<float2*>(&acc[j]);
        const float* pxa = reinterpret_cast<const float*>(&xa[j >> 2]);
        const float* pxb = reinterpret_cast<const float*>(&xb[j >> 2]);
        res.x *= pxa[j & 3];
        res.y *= pxb[j & 3];
        *reinterpret_cast<float2*>(op + (size_t)j * DMODEL) = res;
    }
}

extern "C" void kernel_launch(void* const* d_in, const int* in_sizes, int n_in,
                              void* d_out, int out_size) {
    const float* x1 = (const float*)d_in[0];
    const float* x2 = (const float*)d_in[1];
    const float* v  = (const float*)d_in[2];
    const float* h  = (const float*)d_in[3];
    const float* cb = (const float*)d_in[4];
    float* out = (float*)d_out;

    cudaFuncSetAttribute(hyena_main, cudaFuncAttributeMaxDynamicSharedMemorySize, SMEM_BYTES);

    build_filter<<<NGROUP, LCACHE>>>(h);

    dim3 grid(SEQ_L / T_TILE, DMODEL / (2 * NPAIR), NBATCH);  // (32, 32, 2)
    hyena_main<<<grid, NTHREADS, SMEM_BYTES>>>(x1, x2, v, cb, out);
}